// round 1
// baseline (speedup 1.0000x reference)
#include <cuda_runtime.h>
#include <math.h>

// Problem constants
#define B_  2
#define T_  2048
#define D_  2048
#define H_  16
#define HD_ 128

// ---------------- scratch (static device globals; no allocation) -------------
__device__ float g_q[(size_t)B_ * H_ * T_ * HD_];   // [b,h,t,hd]
__device__ float g_k[(size_t)B_ * H_ * T_ * HD_];
__device__ float g_v[(size_t)B_ * H_ * T_ * HD_];
__device__ float g_y[(size_t)B_ * T_ * D_];         // attention output [b,t,d]

// ============================================================================
// SGEMM 128x128x16, 256 threads, 8x8 micro-tile.
// ============================================================================
__global__ __launch_bounds__(256) void gemm_qkv_kernel(const float* __restrict__ A,
                                                       const float* __restrict__ W)
{
    const int Kd = D_;        // 2048
    const int Nd = 3 * HD_ * H_; // 6144
    __shared__ float As[16][128];
    __shared__ float Bs[16][128];

    int tid = threadIdx.x;
    int m0 = blockIdx.y * 128;
    int n0 = blockIdx.x * 128;
    int ty = tid >> 4, tx = tid & 15;

    float acc[8][8];
#pragma unroll
    for (int i = 0; i < 8; i++)
#pragma unroll
        for (int j = 0; j < 8; j++) acc[i][j] = 0.f;

    for (int k0 = 0; k0 < Kd; k0 += 16) {
#pragma unroll
        for (int i = 0; i < 2; i++) {
            int l = tid * 2 + i;           // 0..511
            int row = l >> 2, c4 = (l & 3) << 2;
            float4 v = *(const float4*)(A + (size_t)(m0 + row) * Kd + k0 + c4);
            As[c4 + 0][row] = v.x; As[c4 + 1][row] = v.y;
            As[c4 + 2][row] = v.z; As[c4 + 3][row] = v.w;
        }
#pragma unroll
        for (int i = 0; i < 2; i++) {
            int l = tid * 2 + i;
            int row = l >> 5, c4 = (l & 31) << 2;
            *(float4*)&Bs[row][c4] = *(const float4*)(W + (size_t)(k0 + row) * Nd + n0 + c4);
        }
        __syncthreads();
#pragma unroll
        for (int kk = 0; kk < 16; kk++) {
            float ra[8], rb[8];
            *(float4*)&ra[0] = *(float4*)&As[kk][ty * 8];
            *(float4*)&ra[4] = *(float4*)&As[kk][ty * 8 + 4];
            *(float4*)&rb[0] = *(float4*)&Bs[kk][tx * 8];
            *(float4*)&rb[4] = *(float4*)&Bs[kk][tx * 8 + 4];
#pragma unroll
            for (int i = 0; i < 8; i++)
#pragma unroll
                for (int j = 0; j < 8; j++) acc[i][j] += ra[i] * rb[j];
        }
        __syncthreads();
    }

    // scatter epilogue into q/k/v  [b,h,t,hd]
#pragma unroll
    for (int i = 0; i < 8; i++) {
        int m = m0 + ty * 8 + i;
        int b = m >> 11, t = m & (T_ - 1);
#pragma unroll
        for (int j = 0; j < 8; j++) {
            int n = n0 + tx * 8 + j;
            int h = n / (3 * HD_);
            int r = n % (3 * HD_);
            size_t base = (((size_t)(b * H_ + h)) * T_ + t) * HD_;
            float val = acc[i][j];
            if (r < HD_)            g_q[base + r]          = val;
            else if (r < 2 * HD_)   g_k[base + r - HD_]    = val;
            else                    g_v[base + r - 2*HD_]  = val;
        }
    }
}

__global__ __launch_bounds__(256) void gemm_out_kernel(const float* __restrict__ W,
                                                       float* __restrict__ C)
{
    const int Kd = D_;   // 2048
    const int Nd = D_;   // 2048
    __shared__ float As[16][128];
    __shared__ float Bs[16][128];

    int tid = threadIdx.x;
    int m0 = blockIdx.y * 128;
    int n0 = blockIdx.x * 128;
    int ty = tid >> 4, tx = tid & 15;

    float acc[8][8];
#pragma unroll
    for (int i = 0; i < 8; i++)
#pragma unroll
        for (int j = 0; j < 8; j++) acc[i][j] = 0.f;

    for (int k0 = 0; k0 < Kd; k0 += 16) {
#pragma unroll
        for (int i = 0; i < 2; i++) {
            int l = tid * 2 + i;
            int row = l >> 2, c4 = (l & 3) << 2;
            float4 v = *(const float4*)(g_y + (size_t)(m0 + row) * Kd + k0 + c4);
            As[c4 + 0][row] = v.x; As[c4 + 1][row] = v.y;
            As[c4 + 2][row] = v.z; As[c4 + 3][row] = v.w;
        }
#pragma unroll
        for (int i = 0; i < 2; i++) {
            int l = tid * 2 + i;
            int row = l >> 5, c4 = (l & 31) << 2;
            *(float4*)&Bs[row][c4] = *(const float4*)(W + (size_t)(k0 + row) * Nd + n0 + c4);
        }
        __syncthreads();
#pragma unroll
        for (int kk = 0; kk < 16; kk++) {
            float ra[8], rb[8];
            *(float4*)&ra[0] = *(float4*)&As[kk][ty * 8];
            *(float4*)&ra[4] = *(float4*)&As[kk][ty * 8 + 4];
            *(float4*)&rb[0] = *(float4*)&Bs[kk][tx * 8];
            *(float4*)&rb[4] = *(float4*)&Bs[kk][tx * 8 + 4];
#pragma unroll
            for (int i = 0; i < 8; i++)
#pragma unroll
                for (int j = 0; j < 8; j++) acc[i][j] += ra[i] * rb[j];
        }
        __syncthreads();
    }

#pragma unroll
    for (int i = 0; i < 8; i++) {
        size_t m = m0 + ty * 8 + i;
        float* cp = C + m * Nd + n0 + tx * 8;
        float4 v0 = make_float4(acc[i][0], acc[i][1], acc[i][2], acc[i][3]);
        float4 v1 = make_float4(acc[i][4], acc[i][5], acc[i][6], acc[i][7]);
        *(float4*)(cp)     = v0;
        *(float4*)(cp + 4) = v1;
    }
}

// ============================================================================
// RoPE (interleaved) applied in place to g_q, g_k.
// ============================================================================
__global__ void rope_kernel()
{
    int idx = blockIdx.x * blockDim.x + threadIdx.x;
    const int total = B_ * H_ * T_ * (HD_ / 2);
    if (idx >= total) return;
    int i = idx & 63;                 // freq index 0..63
    int t = (idx >> 6) & (T_ - 1);    // position
    float inv = powf(10000.0f, -((float)(2 * i)) * (1.0f / 128.0f));
    float ang = (float)t * inv;
    float s, c;
    sincosf(ang, &s, &c);
    size_t off = ((size_t)(idx >> 6)) * HD_ + 2 * i;
    float q1 = g_q[off], q2 = g_q[off + 1];
    g_q[off]     = q1 * c - q2 * s;
    g_q[off + 1] = q1 * s + q2 * c;
    float k1 = g_k[off], k2 = g_k[off + 1];
    g_k[off]     = k1 * c - k2 * s;
    g_k[off + 1] = k1 * s + k2 * c;
}

// ============================================================================
// Flash attention, fp32. BM=BN=64, HD=128, 256 threads (16x16).
// QT/KT stored transposed [kk][row] (pad 65) for conflict-free S loop.
// V reuses KT buffer, row-major [64][128].
// Thread (ty,tx): S rows {ty+16i}, S cols {tx+16j}; O cols {tx*8+c}.
// ============================================================================
#define ATTN_SMEM_FLOATS (128*65 + 128*65 + 64*65)
__global__ __launch_bounds__(256, 2) void attn_kernel()
{
    extern __shared__ float sm[];
    float* QT = sm;                  // [128][65]  QT[kk*65 + row]
    float* KT = sm + 128 * 65;       // [128][65]  (also V: [64][128])
    float* Ps = sm + 2 * 128 * 65;   // [64][65]
    float* Vs = KT;

    int b = blockIdx.z, h = blockIdx.y;
    int q0 = blockIdx.x * 64;
    const float* Qh = g_q + (((size_t)(b * H_ + h)) * T_) * HD_;
    const float* Kh = g_k + (((size_t)(b * H_ + h)) * T_) * HD_;
    const float* Vh = g_v + (((size_t)(b * H_ + h)) * T_) * HD_;

    int tid = threadIdx.x;
    int ty = tid >> 4, tx = tid & 15;

    // load Q tile (64x128) transposed into QT
    for (int l = tid; l < 64 * 32; l += 256) {
        int row = l >> 5, c4 = (l & 31) << 2;
        float4 v = *(const float4*)(Qh + (size_t)(q0 + row) * HD_ + c4);
        QT[(c4 + 0) * 65 + row] = v.x;
        QT[(c4 + 1) * 65 + row] = v.y;
        QT[(c4 + 2) * 65 + row] = v.z;
        QT[(c4 + 3) * 65 + row] = v.w;
    }

    float m_i[4], l_i[4], o[4][8];
#pragma unroll
    for (int i = 0; i < 4; i++) {
        m_i[i] = -1e30f; l_i[i] = 0.f;
#pragma unroll
        for (int c = 0; c < 8; c++) o[i][c] = 0.f;
    }
    const float sm_scale = 0.08838834764831845f;  // 1/sqrt(128)

    for (int k0 = 0; k0 <= q0; k0 += 64) {
        __syncthreads();   // protect KT/Vs from previous iteration readers
        // load K tile transposed
        for (int l = tid; l < 64 * 32; l += 256) {
            int row = l >> 5, c4 = (l & 31) << 2;
            float4 v = *(const float4*)(Kh + (size_t)(k0 + row) * HD_ + c4);
            KT[(c4 + 0) * 65 + row] = v.x;
            KT[(c4 + 1) * 65 + row] = v.y;
            KT[(c4 + 2) * 65 + row] = v.z;
            KT[(c4 + 3) * 65 + row] = v.w;
        }
        __syncthreads();

        // S = Q K^T
        float s[4][4];
#pragma unroll
        for (int i = 0; i < 4; i++)
#pragma unroll
            for (int j = 0; j < 4; j++) s[i][j] = 0.f;

#pragma unroll 4
        for (int kk = 0; kk < 128; kk++) {
            float rq[4], rk[4];
#pragma unroll
            for (int i = 0; i < 4; i++) rq[i] = QT[kk * 65 + ty + 16 * i];
#pragma unroll
            for (int j = 0; j < 4; j++) rk[j] = KT[kk * 65 + tx + 16 * j];
#pragma unroll
            for (int i = 0; i < 4; i++)
#pragma unroll
                for (int j = 0; j < 4; j++) s[i][j] += rq[i] * rk[j];
        }

        bool diag = (k0 == q0);
#pragma unroll
        for (int i = 0; i < 4; i++) {
#pragma unroll
            for (int j = 0; j < 4; j++) {
                s[i][j] *= sm_scale;
                if (diag && (k0 + tx + 16 * j > q0 + ty + 16 * i)) s[i][j] = -1e30f;
            }
        }

        // online softmax per row; reduce across 16-lane groups (same ty)
#pragma unroll
        for (int i = 0; i < 4; i++) {
            float mx = fmaxf(fmaxf(s[i][0], s[i][1]), fmaxf(s[i][2], s[i][3]));
#pragma unroll
            for (int w = 1; w < 16; w <<= 1)
                mx = fmaxf(mx, __shfl_xor_sync(0xffffffffu, mx, w));
            float mnew = fmaxf(m_i[i], mx);
            float sum = 0.f;
#pragma unroll
            for (int j = 0; j < 4; j++) {
                s[i][j] = __expf(s[i][j] - mnew);
                sum += s[i][j];
            }
#pragma unroll
            for (int w = 1; w < 16; w <<= 1)
                sum += __shfl_xor_sync(0xffffffffu, sum, w);
            float sc = __expf(m_i[i] - mnew);
            l_i[i] = l_i[i] * sc + sum;
            m_i[i] = mnew;
#pragma unroll
            for (int c = 0; c < 8; c++) o[i][c] *= sc;
#pragma unroll
            for (int j = 0; j < 4; j++)
                Ps[(ty + 16 * i) * 65 + tx + 16 * j] = s[i][j];
        }
        __syncthreads();   // S-phase readers of KT done; Ps written

        // load V tile row-major, overwriting KT
        for (int l = tid; l < 64 * 32; l += 256) {
            int row = l >> 5, c4 = (l & 31) << 2;
            float4 v = *(const float4*)(Vh + (size_t)(k0 + row) * HD_ + c4);
            *(float4*)&Vs[row * 128 + c4] = v;
        }
        __syncthreads();

        // O += P V
#pragma unroll 2
        for (int j = 0; j < 64; j++) {
            float pv[4];
#pragma unroll
            for (int i = 0; i < 4; i++) pv[i] = Ps[(ty + 16 * i) * 65 + j];
            float vv[8];
            *(float4*)&vv[0] = *(float4*)&Vs[j * 128 + tx * 8];
            *(float4*)&vv[4] = *(float4*)&Vs[j * 128 + tx * 8 + 4];
#pragma unroll
            for (int i = 0; i < 4; i++)
#pragma unroll
                for (int c = 0; c < 8; c++) o[i][c] += pv[i] * vv[c];
        }
    }

    // write y[b, q0+row, h*128 + col]
#pragma unroll
    for (int i = 0; i < 4; i++) {
        float inv_l = 1.0f / l_i[i];
        size_t row = (size_t)b * T_ + q0 + ty + 16 * i;
        float* yp = g_y + row * D_ + h * HD_ + tx * 8;
        float4 v0 = make_float4(o[i][0] * inv_l, o[i][1] * inv_l,
                                o[i][2] * inv_l, o[i][3] * inv_l);
        float4 v1 = make_float4(o[i][4] * inv_l, o[i][5] * inv_l,
                                o[i][6] * inv_l, o[i][7] * inv_l);
        *(float4*)(yp)     = v0;
        *(float4*)(yp + 4) = v1;
    }
}

// ============================================================================
extern "C" void kernel_launch(void* const* d_in, const int* in_sizes, int n_in,
                              void* d_out, int out_size)
{
    const float* x     = (const float*)d_in[0];
    const float* w_qkv = (const float*)d_in[1];
    const float* w_out = (const float*)d_in[2];
    float* out = (float*)d_out;

    size_t attn_smem = (size_t)ATTN_SMEM_FLOATS * sizeof(float);
    cudaFuncSetAttribute(attn_kernel, cudaFuncAttributeMaxDynamicSharedMemorySize,
                         (int)attn_smem);

    dim3 g1(6144 / 128, (B_ * T_) / 128);
    gemm_qkv_kernel<<<g1, 256>>>(x, w_qkv);

    int total_pairs = B_ * H_ * T_ * (HD_ / 2);
    rope_kernel<<<(total_pairs + 255) / 256, 256>>>();

    dim3 g2(T_ / 64, H_, B_);
    attn_kernel<<<g2, 256, attn_smem>>>();

    dim3 g3(D_ / 128, (B_ * T_) / 128);
    gemm_out_kernel<<<g3, 256>>>(w_out, out);
}

// round 3
// speedup vs baseline: 1.8001x; 1.8001x over previous
#include <cuda_runtime.h>
#include <math.h>

// Problem constants
#define B_  2
#define T_  2048
#define D_  2048
#define H_  16
#define HD_ 128

// ---------------- scratch (static device globals; no allocation) -------------
__device__ float g_q[(size_t)B_ * H_ * T_ * HD_];   // [b,h,t,hd]
__device__ float g_k[(size_t)B_ * H_ * T_ * HD_];
__device__ float g_v[(size_t)B_ * H_ * T_ * HD_];
__device__ float g_y[(size_t)B_ * T_ * D_];         // attention output [b,t,d]

// ============================================================================
// tf32 mma helpers
// ============================================================================
__device__ __forceinline__ unsigned f2tf32(float x) {
    unsigned r;
    asm("cvt.rna.tf32.f32 %0, %1;" : "=r"(r) : "f"(x));
    return r;
}

__device__ __forceinline__ void mma_tf32(float c[4],
                                         unsigned a0, unsigned a1, unsigned a2, unsigned a3,
                                         unsigned b0, unsigned b1) {
    asm volatile(
        "mma.sync.aligned.m16n8k8.row.col.f32.tf32.tf32.f32 "
        "{%0,%1,%2,%3}, {%4,%5,%6,%7}, {%8,%9}, {%0,%1,%2,%3};"
        : "+f"(c[0]), "+f"(c[1]), "+f"(c[2]), "+f"(c[3])
        : "r"(a0), "r"(a1), "r"(a2), "r"(a3), "r"(b0), "r"(b1));
}

// Smem layout constants
#define A_STRIDE 36    // 32 k-slots permuted + pad, conflict-free LDS.128
#define B_STRIDE 132   // 128 n + pad, conflict-free STS.128

struct GemmCtx {
    int m0, n0, lane, warp_m, warp_n;
};

// ---------------- epilogue functors ------------------------------------------
__device__ __forceinline__ void qkv_scatter(int row, int col, float val)
{
    int b = row >> 11, t = row & (T_ - 1);
    int h = col / (3 * HD_);
    int r = col % (3 * HD_);
    size_t base = (((size_t)(b * H_ + h)) * T_ + t) * HD_;
    if (r < HD_)          g_q[base + r] = val;
    else if (r < 2 * HD_) g_k[base + r - HD_] = val;
    else                  g_v[base + r - 2 * HD_] = val;
}

struct QkvEpi {
    __device__ __forceinline__ void operator()(const GemmCtx& c, float acc[4][4][4]) const {
#pragma unroll
        for (int mt = 0; mt < 4; mt++) {
            int row = c.m0 + c.warp_m * 64 + mt * 16 + (c.lane >> 2);
#pragma unroll
            for (int nt = 0; nt < 4; nt++) {
                int col = c.n0 + c.warp_n * 32 + nt * 8 + (c.lane & 3) * 2;
                qkv_scatter(row,     col,     acc[mt][nt][0]);
                qkv_scatter(row,     col + 1, acc[mt][nt][1]);
                qkv_scatter(row + 8, col,     acc[mt][nt][2]);
                qkv_scatter(row + 8, col + 1, acc[mt][nt][3]);
            }
        }
    }
};

struct OutEpi {
    float* C;
    __device__ __forceinline__ void operator()(const GemmCtx& c, float acc[4][4][4]) const {
#pragma unroll
        for (int mt = 0; mt < 4; mt++) {
            int row = c.m0 + c.warp_m * 64 + mt * 16 + (c.lane >> 2);
#pragma unroll
            for (int nt = 0; nt < 4; nt++) {
                int col = c.n0 + c.warp_n * 32 + nt * 8 + (c.lane & 3) * 2;
                *(float2*)(C + (size_t)row * D_ + col) =
                    make_float2(acc[mt][nt][0], acc[mt][nt][1]);
                *(float2*)(C + (size_t)(row + 8) * D_ + col) =
                    make_float2(acc[mt][nt][2], acc[mt][nt][3]);
            }
        }
    }
};

// ============================================================================
// tf32 tensor-core GEMM 128x128x32, 256 threads (8 warps, 2m x 4n),
// warp tile 64x32 (4 m-tiles x 4 n-tiles of m16n8k8).
// A: row-major [M][K]; B: row-major [K][N]. Register-staged double buffer.
// ============================================================================
template <typename Epi>
__device__ __forceinline__ void gemm_tf32_body(const float* __restrict__ A,
                                               const float* __restrict__ Bg,
                                               int Kd, int Nd, Epi epi)
{
    __shared__ unsigned As[128 * A_STRIDE];
    __shared__ unsigned Bs[32 * B_STRIDE];

    const int tid = threadIdx.x;
    const int lane = tid & 31;
    const int warp = tid >> 5;
    const int warp_m = warp & 1;   // 0..1 -> 64 rows
    const int warp_n = warp >> 1;  // 0..3 -> 32 cols
    const int m0 = blockIdx.y * 128;
    const int n0 = blockIdx.x * 128;

    float acc[4][4][4];
#pragma unroll
    for (int mt = 0; mt < 4; mt++)
#pragma unroll
        for (int nt = 0; nt < 4; nt++)
#pragma unroll
            for (int e = 0; e < 4; e++) acc[mt][nt][e] = 0.f;

    float4 aS[4], bS[4];
#pragma unroll
    for (int i = 0; i < 4; i++) {
        int l = tid + 256 * i;
        int ar = l >> 3, ac = (l & 7) << 2;
        aS[i] = *(const float4*)(A + (size_t)(m0 + ar) * Kd + ac);
        int kr = l >> 5, bc = (l & 31) << 2;
        bS[i] = *(const float4*)(Bg + (size_t)kr * Nd + n0 + bc);
    }

    for (int k0 = 0; k0 < Kd; k0 += 32) {
        // ---- STS (with tf32 convert) ----
#pragma unroll
        for (int i = 0; i < 4; i++) {
            int l = tid + 256 * i;
            int ar = l >> 3, ac = (l & 7) << 2;
            unsigned* dst = &As[ar * A_STRIDE];
            float v[4] = {aS[i].x, aS[i].y, aS[i].z, aS[i].w};
#pragma unroll
            for (int e = 0; e < 4; e++) {
                int k = ac + e;
                dst[(k & 3) * 8 + (k >> 2)] = f2tf32(v[e]);
            }
            int kr = l >> 5, bc = (l & 31) << 2;
            uint4 bv;
            bv.x = f2tf32(bS[i].x); bv.y = f2tf32(bS[i].y);
            bv.z = f2tf32(bS[i].z); bv.w = f2tf32(bS[i].w);
            *(uint4*)&Bs[kr * B_STRIDE + bc] = bv;
        }
        __syncthreads();

        // ---- prefetch next tile into regs ----
        if (k0 + 32 < Kd) {
#pragma unroll
            for (int i = 0; i < 4; i++) {
                int l = tid + 256 * i;
                int ar = l >> 3, ac = (l & 7) << 2;
                aS[i] = *(const float4*)(A + (size_t)(m0 + ar) * Kd + k0 + 32 + ac);
                int kr = l >> 5, bc = (l & 31) << 2;
                bS[i] = *(const float4*)(Bg + (size_t)(k0 + 32 + kr) * Nd + n0 + bc);
            }
        }

        // ---- compute: 4 k-steps in 2 halves ----
#pragma unroll
        for (int h = 0; h < 2; h++) {
            uint4 alo[4], ahi[4];
#pragma unroll
            for (int mt = 0; mt < 4; mt++) {
                int r0 = warp_m * 64 + mt * 16 + (lane >> 2);
                int cbase = (lane & 3) * 8 + h * 4;
                alo[mt] = *(uint4*)&As[r0 * A_STRIDE + cbase];
                ahi[mt] = *(uint4*)&As[(r0 + 8) * A_STRIDE + cbase];
            }
#pragma unroll
            for (int sh = 0; sh < 2; sh++) {
                int s = 2 * h + sh;
                unsigned b0[4], b1[4];
#pragma unroll
                for (int nt = 0; nt < 4; nt++) {
                    int col = warp_n * 32 + nt * 8 + (lane >> 2);
                    b0[nt] = Bs[(8 * s + (lane & 3)) * B_STRIDE + col];
                    b1[nt] = Bs[(8 * s + 4 + (lane & 3)) * B_STRIDE + col];
                }
#pragma unroll
                for (int mt = 0; mt < 4; mt++) {
                    unsigned a0 = sh ? alo[mt].z : alo[mt].x;
                    unsigned a1 = sh ? ahi[mt].z : ahi[mt].x;
                    unsigned a2 = sh ? alo[mt].w : alo[mt].y;
                    unsigned a3 = sh ? ahi[mt].w : ahi[mt].y;
#pragma unroll
                    for (int nt = 0; nt < 4; nt++)
                        mma_tf32(acc[mt][nt], a0, a1, a2, a3, b0[nt], b1[nt]);
                }
            }
        }
        __syncthreads();
    }

    GemmCtx ctx{m0, n0, lane, warp_m, warp_n};
    epi(ctx, acc);
}

__global__ __launch_bounds__(256, 1) void gemm_qkv_kernel(const float* __restrict__ A,
                                                          const float* __restrict__ W)
{
    gemm_tf32_body(A, W, D_, 3 * HD_ * H_, QkvEpi{});
}

__global__ __launch_bounds__(256, 1) void gemm_out_kernel(const float* __restrict__ W,
                                                          float* __restrict__ C)
{
    gemm_tf32_body(g_y, W, D_, D_, OutEpi{C});
}

// ============================================================================
// RoPE (interleaved) applied in place to g_q, g_k.
// ============================================================================
__global__ void rope_kernel()
{
    int idx = blockIdx.x * blockDim.x + threadIdx.x;
    const int total = B_ * H_ * T_ * (HD_ / 2);
    if (idx >= total) return;
    int i = idx & 63;                 // freq index 0..63
    int t = (idx >> 6) & (T_ - 1);    // position
    float inv = powf(10000.0f, -((float)(2 * i)) * (1.0f / 128.0f));
    float ang = (float)t * inv;
    float s, c;
    sincosf(ang, &s, &c);
    size_t off = ((size_t)(idx >> 6)) * HD_ + 2 * i;
    float q1 = g_q[off], q2 = g_q[off + 1];
    g_q[off]     = q1 * c - q2 * s;
    g_q[off + 1] = q1 * s + q2 * c;
    float k1 = g_k[off], k2 = g_k[off + 1];
    g_k[off]     = k1 * c - k2 * s;
    g_k[off + 1] = k1 * s + k2 * c;
}

// ============================================================================
// Flash attention, fp32. BM=BN=64, HD=128, 256 threads (16x16). (unchanged)
// ============================================================================
#define ATTN_SMEM_FLOATS (128*65 + 128*65 + 64*65)
__global__ __launch_bounds__(256, 2) void attn_kernel()
{
    extern __shared__ float sm[];
    float* QT = sm;                  // [128][65]  QT[kk*65 + row]
    float* KT = sm + 128 * 65;       // [128][65]  (also V: [64][128])
    float* Ps = sm + 2 * 128 * 65;   // [64][65]
    float* Vs = KT;

    int b = blockIdx.z, h = blockIdx.y;
    int q0 = blockIdx.x * 64;
    const float* Qh = g_q + (((size_t)(b * H_ + h)) * T_) * HD_;
    const float* Kh = g_k + (((size_t)(b * H_ + h)) * T_) * HD_;
    const float* Vh = g_v + (((size_t)(b * H_ + h)) * T_) * HD_;

    int tid = threadIdx.x;
    int ty = tid >> 4, tx = tid & 15;

    for (int l = tid; l < 64 * 32; l += 256) {
        int row = l >> 5, c4 = (l & 31) << 2;
        float4 v = *(const float4*)(Qh + (size_t)(q0 + row) * HD_ + c4);
        QT[(c4 + 0) * 65 + row] = v.x;
        QT[(c4 + 1) * 65 + row] = v.y;
        QT[(c4 + 2) * 65 + row] = v.z;
        QT[(c4 + 3) * 65 + row] = v.w;
    }

    float m_i[4], l_i[4], o[4][8];
#pragma unroll
    for (int i = 0; i < 4; i++) {
        m_i[i] = -1e30f; l_i[i] = 0.f;
#pragma unroll
        for (int c = 0; c < 8; c++) o[i][c] = 0.f;
    }
    const float sm_scale = 0.08838834764831845f;  // 1/sqrt(128)

    for (int k0 = 0; k0 <= q0; k0 += 64) {
        __syncthreads();
        for (int l = tid; l < 64 * 32; l += 256) {
            int row = l >> 5, c4 = (l & 31) << 2;
            float4 v = *(const float4*)(Kh + (size_t)(k0 + row) * HD_ + c4);
            KT[(c4 + 0) * 65 + row] = v.x;
            KT[(c4 + 1) * 65 + row] = v.y;
            KT[(c4 + 2) * 65 + row] = v.z;
            KT[(c4 + 3) * 65 + row] = v.w;
        }
        __syncthreads();

        float s[4][4];
#pragma unroll
        for (int i = 0; i < 4; i++)
#pragma unroll
            for (int j = 0; j < 4; j++) s[i][j] = 0.f;

#pragma unroll 4
        for (int kk = 0; kk < 128; kk++) {
            float rq[4], rk[4];
#pragma unroll
            for (int i = 0; i < 4; i++) rq[i] = QT[kk * 65 + ty + 16 * i];
#pragma unroll
            for (int j = 0; j < 4; j++) rk[j] = KT[kk * 65 + tx + 16 * j];
#pragma unroll
            for (int i = 0; i < 4; i++)
#pragma unroll
                for (int j = 0; j < 4; j++) s[i][j] += rq[i] * rk[j];
        }

        bool diag = (k0 == q0);
#pragma unroll
        for (int i = 0; i < 4; i++) {
#pragma unroll
            for (int j = 0; j < 4; j++) {
                s[i][j] *= sm_scale;
                if (diag && (k0 + tx + 16 * j > q0 + ty + 16 * i)) s[i][j] = -1e30f;
            }
        }

#pragma unroll
        for (int i = 0; i < 4; i++) {
            float mx = fmaxf(fmaxf(s[i][0], s[i][1]), fmaxf(s[i][2], s[i][3]));
#pragma unroll
            for (int w = 1; w < 16; w <<= 1)
                mx = fmaxf(mx, __shfl_xor_sync(0xffffffffu, mx, w));
            float mnew = fmaxf(m_i[i], mx);
            float sum = 0.f;
#pragma unroll
            for (int j = 0; j < 4; j++) {
                s[i][j] = __expf(s[i][j] - mnew);
                sum += s[i][j];
            }
#pragma unroll
            for (int w = 1; w < 16; w <<= 1)
                sum += __shfl_xor_sync(0xffffffffu, sum, w);
            float sc = __expf(m_i[i] - mnew);
            l_i[i] = l_i[i] * sc + sum;
            m_i[i] = mnew;
#pragma unroll
            for (int c = 0; c < 8; c++) o[i][c] *= sc;
#pragma unroll
            for (int j = 0; j < 4; j++)
                Ps[(ty + 16 * i) * 65 + tx + 16 * j] = s[i][j];
        }
        __syncthreads();

        for (int l = tid; l < 64 * 32; l += 256) {
            int row = l >> 5, c4 = (l & 31) << 2;
            float4 v = *(const float4*)(Vh + (size_t)(k0 + row) * HD_ + c4);
            *(float4*)&Vs[row * 128 + c4] = v;
        }
        __syncthreads();

#pragma unroll 2
        for (int j = 0; j < 64; j++) {
            float pv[4];
#pragma unroll
            for (int i = 0; i < 4; i++) pv[i] = Ps[(ty + 16 * i) * 65 + j];
            float vv[8];
            *(float4*)&vv[0] = *(float4*)&Vs[j * 128 + tx * 8];
            *(float4*)&vv[4] = *(float4*)&Vs[j * 128 + tx * 8 + 4];
#pragma unroll
            for (int i = 0; i < 4; i++)
#pragma unroll
                for (int c = 0; c < 8; c++) o[i][c] += pv[i] * vv[c];
        }
    }

#pragma unroll
    for (int i = 0; i < 4; i++) {
        float inv_l = 1.0f / l_i[i];
        size_t row = (size_t)b * T_ + q0 + ty + 16 * i;
        float* yp = g_y + row * D_ + h * HD_ + tx * 8;
        float4 v0 = make_float4(o[i][0] * inv_l, o[i][1] * inv_l,
                                o[i][2] * inv_l, o[i][3] * inv_l);
        float4 v1 = make_float4(o[i][4] * inv_l, o[i][5] * inv_l,
                                o[i][6] * inv_l, o[i][7] * inv_l);
        *(float4*)(yp)     = v0;
        *(float4*)(yp + 4) = v1;
    }
}

// ============================================================================
extern "C" void kernel_launch(void* const* d_in, const int* in_sizes, int n_in,
                              void* d_out, int out_size)
{
    const float* x     = (const float*)d_in[0];
    const float* w_qkv = (const float*)d_in[1];
    const float* w_out = (const float*)d_in[2];
    float* out = (float*)d_out;

    size_t attn_smem = (size_t)ATTN_SMEM_FLOATS * sizeof(float);
    cudaFuncSetAttribute(attn_kernel, cudaFuncAttributeMaxDynamicSharedMemorySize,
                         (int)attn_smem);

    dim3 g1(6144 / 128, (B_ * T_) / 128);
    gemm_qkv_kernel<<<g1, 256>>>(x, w_qkv);

    int total_pairs = B_ * H_ * T_ * (HD_ / 2);
    rope_kernel<<<(total_pairs + 255) / 256, 256>>>();

    dim3 g2(T_ / 64, H_, B_);
    attn_kernel<<<g2, 256, attn_smem>>>();

    dim3 g3(D_ / 128, (B_ * T_) / 128);
    gemm_out_kernel<<<g3, 256>>>(w_out, out);
}

// round 4
// speedup vs baseline: 3.0771x; 1.7094x over previous
#include <cuda_runtime.h>
#include <math.h>

// Problem constants
#define B_  2
#define T_  2048
#define D_  2048
#define H_  16
#define HD_ 128

// ---------------- scratch (static device globals; no allocation) -------------
__device__ float g_q[(size_t)B_ * H_ * T_ * HD_];   // [b,h,t,hd]  (tf32-rounded after rope)
__device__ float g_k[(size_t)B_ * H_ * T_ * HD_];   // (tf32-rounded after rope)
__device__ float g_v[(size_t)B_ * H_ * T_ * HD_];   // (tf32-rounded at epilogue)
__device__ float g_y[(size_t)B_ * T_ * D_];         // attention output [b,t,d]

// ============================================================================
// tf32 mma helpers
// ============================================================================
__device__ __forceinline__ unsigned f2tf32(float x) {
    unsigned r;
    asm("cvt.rna.tf32.f32 %0, %1;" : "=r"(r) : "f"(x));
    return r;
}

__device__ __forceinline__ void mma_tf32(float c[4],
                                         unsigned a0, unsigned a1, unsigned a2, unsigned a3,
                                         unsigned b0, unsigned b1) {
    asm volatile(
        "mma.sync.aligned.m16n8k8.row.col.f32.tf32.tf32.f32 "
        "{%0,%1,%2,%3}, {%4,%5,%6,%7}, {%8,%9}, {%0,%1,%2,%3};"
        : "+f"(c[0]), "+f"(c[1]), "+f"(c[2]), "+f"(c[3])
        : "r"(a0), "r"(a1), "r"(a2), "r"(a3), "r"(b0), "r"(b1));
}

// cp.async helpers
__device__ __forceinline__ void cpa16(float* dst, const float* src) {
    unsigned s = (unsigned)__cvta_generic_to_shared(dst);
    asm volatile("cp.async.cg.shared.global [%0], [%1], 16;" :: "r"(s), "l"(src));
}
__device__ __forceinline__ void cpa_commit() { asm volatile("cp.async.commit_group;"); }
template<int N> __device__ __forceinline__ void cpa_wait() {
    asm volatile("cp.async.wait_group %0;" :: "n"(N));
}

// Smem layout constants (projection GEMM)
#define A_STRIDE 36    // 32 k-slots permuted + pad, conflict-free LDS.128
#define B_STRIDE 132   // 128 n + pad, conflict-free STS.128

struct GemmCtx {
    int m0, n0, lane, warp_m, warp_n;
};

// ---------------- epilogue functors ------------------------------------------
__device__ __forceinline__ void qkv_scatter(int row, int col, float val)
{
    int b = row >> 11, t = row & (T_ - 1);
    int h = col / (3 * HD_);
    int r = col % (3 * HD_);
    size_t base = (((size_t)(b * H_ + h)) * T_ + t) * HD_;
    if (r < HD_)          g_q[base + r] = val;
    else if (r < 2 * HD_) g_k[base + r - HD_] = val;
    else                  g_v[base + r - 2 * HD_] = __uint_as_float(f2tf32(val));
}

struct QkvEpi {
    __device__ __forceinline__ void operator()(const GemmCtx& c, float acc[4][4][4]) const {
#pragma unroll
        for (int mt = 0; mt < 4; mt++) {
            int row = c.m0 + c.warp_m * 64 + mt * 16 + (c.lane >> 2);
#pragma unroll
            for (int nt = 0; nt < 4; nt++) {
                int col = c.n0 + c.warp_n * 32 + nt * 8 + (c.lane & 3) * 2;
                qkv_scatter(row,     col,     acc[mt][nt][0]);
                qkv_scatter(row,     col + 1, acc[mt][nt][1]);
                qkv_scatter(row + 8, col,     acc[mt][nt][2]);
                qkv_scatter(row + 8, col + 1, acc[mt][nt][3]);
            }
        }
    }
};

struct OutEpi {
    float* C;
    __device__ __forceinline__ void operator()(const GemmCtx& c, float acc[4][4][4]) const {
#pragma unroll
        for (int mt = 0; mt < 4; mt++) {
            int row = c.m0 + c.warp_m * 64 + mt * 16 + (c.lane >> 2);
#pragma unroll
            for (int nt = 0; nt < 4; nt++) {
                int col = c.n0 + c.warp_n * 32 + nt * 8 + (c.lane & 3) * 2;
                *(float2*)(C + (size_t)row * D_ + col) =
                    make_float2(acc[mt][nt][0], acc[mt][nt][1]);
                *(float2*)(C + (size_t)(row + 8) * D_ + col) =
                    make_float2(acc[mt][nt][2], acc[mt][nt][3]);
            }
        }
    }
};

// ============================================================================
// tf32 tensor-core GEMM 128x128x32, 256 threads (8 warps, 2m x 4n).
// ============================================================================
template <typename Epi>
__device__ __forceinline__ void gemm_tf32_body(const float* __restrict__ A,
                                               const float* __restrict__ Bg,
                                               int Kd, int Nd, Epi epi)
{
    __shared__ unsigned As[128 * A_STRIDE];
    __shared__ unsigned Bs[32 * B_STRIDE];

    const int tid = threadIdx.x;
    const int lane = tid & 31;
    const int warp = tid >> 5;
    const int warp_m = warp & 1;
    const int warp_n = warp >> 1;
    const int m0 = blockIdx.y * 128;
    const int n0 = blockIdx.x * 128;

    float acc[4][4][4];
#pragma unroll
    for (int mt = 0; mt < 4; mt++)
#pragma unroll
        for (int nt = 0; nt < 4; nt++)
#pragma unroll
            for (int e = 0; e < 4; e++) acc[mt][nt][e] = 0.f;

    float4 aS[4], bS[4];
#pragma unroll
    for (int i = 0; i < 4; i++) {
        int l = tid + 256 * i;
        int ar = l >> 3, ac = (l & 7) << 2;
        aS[i] = *(const float4*)(A + (size_t)(m0 + ar) * Kd + ac);
        int kr = l >> 5, bc = (l & 31) << 2;
        bS[i] = *(const float4*)(Bg + (size_t)kr * Nd + n0 + bc);
    }

    for (int k0 = 0; k0 < Kd; k0 += 32) {
#pragma unroll
        for (int i = 0; i < 4; i++) {
            int l = tid + 256 * i;
            int ar = l >> 3, ac = (l & 7) << 2;
            unsigned* dst = &As[ar * A_STRIDE];
            float v[4] = {aS[i].x, aS[i].y, aS[i].z, aS[i].w};
#pragma unroll
            for (int e = 0; e < 4; e++) {
                int k = ac + e;
                dst[(k & 3) * 8 + (k >> 2)] = f2tf32(v[e]);
            }
            int kr = l >> 5, bc = (l & 31) << 2;
            uint4 bv;
            bv.x = f2tf32(bS[i].x); bv.y = f2tf32(bS[i].y);
            bv.z = f2tf32(bS[i].z); bv.w = f2tf32(bS[i].w);
            *(uint4*)&Bs[kr * B_STRIDE + bc] = bv;
        }
        __syncthreads();

        if (k0 + 32 < Kd) {
#pragma unroll
            for (int i = 0; i < 4; i++) {
                int l = tid + 256 * i;
                int ar = l >> 3, ac = (l & 7) << 2;
                aS[i] = *(const float4*)(A + (size_t)(m0 + ar) * Kd + k0 + 32 + ac);
                int kr = l >> 5, bc = (l & 31) << 2;
                bS[i] = *(const float4*)(Bg + (size_t)(k0 + 32 + kr) * Nd + n0 + bc);
            }
        }

#pragma unroll
        for (int h = 0; h < 2; h++) {
            uint4 alo[4], ahi[4];
#pragma unroll
            for (int mt = 0; mt < 4; mt++) {
                int r0 = warp_m * 64 + mt * 16 + (lane >> 2);
                int cbase = (lane & 3) * 8 + h * 4;
                alo[mt] = *(uint4*)&As[r0 * A_STRIDE + cbase];
                ahi[mt] = *(uint4*)&As[(r0 + 8) * A_STRIDE + cbase];
            }
#pragma unroll
            for (int sh = 0; sh < 2; sh++) {
                int s = 2 * h + sh;
                unsigned b0[4], b1[4];
#pragma unroll
                for (int nt = 0; nt < 4; nt++) {
                    int col = warp_n * 32 + nt * 8 + (lane >> 2);
                    b0[nt] = Bs[(8 * s + (lane & 3)) * B_STRIDE + col];
                    b1[nt] = Bs[(8 * s + 4 + (lane & 3)) * B_STRIDE + col];
                }
#pragma unroll
                for (int mt = 0; mt < 4; mt++) {
                    unsigned a0 = sh ? alo[mt].z : alo[mt].x;
                    unsigned a1 = sh ? ahi[mt].z : ahi[mt].x;
                    unsigned a2 = sh ? alo[mt].w : alo[mt].y;
                    unsigned a3 = sh ? ahi[mt].w : ahi[mt].y;
#pragma unroll
                    for (int nt = 0; nt < 4; nt++)
                        mma_tf32(acc[mt][nt], a0, a1, a2, a3, b0[nt], b1[nt]);
                }
            }
        }
        __syncthreads();
    }

    GemmCtx ctx{m0, n0, lane, warp_m, warp_n};
    epi(ctx, acc);
}

__global__ __launch_bounds__(256, 1) void gemm_qkv_kernel(const float* __restrict__ A,
                                                          const float* __restrict__ W)
{
    gemm_tf32_body(A, W, D_, 3 * HD_ * H_, QkvEpi{});
}

__global__ __launch_bounds__(256, 1) void gemm_out_kernel(const float* __restrict__ W,
                                                          float* __restrict__ C)
{
    gemm_tf32_body(g_y, W, D_, D_, OutEpi{C});
}

// ============================================================================
// RoPE (interleaved) in place on g_q, g_k; outputs tf32-rounded so the
// attention MMAs can consume raw bits with no cvt.
// ============================================================================
__global__ void rope_kernel()
{
    int idx = blockIdx.x * blockDim.x + threadIdx.x;
    const int total = B_ * H_ * T_ * (HD_ / 2);
    if (idx >= total) return;
    int i = idx & 63;
    int t = (idx >> 6) & (T_ - 1);
    float inv = powf(10000.0f, -((float)(2 * i)) * (1.0f / 128.0f));
    float ang = (float)t * inv;
    float s, c;
    sincosf(ang, &s, &c);
    size_t off = ((size_t)(idx >> 6)) * HD_ + 2 * i;
    float q1 = g_q[off], q2 = g_q[off + 1];
    g_q[off]     = __uint_as_float(f2tf32(q1 * c - q2 * s));
    g_q[off + 1] = __uint_as_float(f2tf32(q1 * s + q2 * c));
    float k1 = g_k[off], k2 = g_k[off + 1];
    g_k[off]     = __uint_as_float(f2tf32(k1 * c - k2 * s));
    g_k[off + 1] = __uint_as_float(f2tf32(k1 * s + k2 * c));
}

// ============================================================================
// Flash attention on tensor cores (tf32 mma.m16n8k8).
// BM=128, BN=64, HD=128. 256 threads = 8 warps, warp w owns q-rows [16w,16w+16).
// Q fragments in registers (loaded once). K/V double-buffered via cp.async.
// ============================================================================
#define KV_STR 132     // 128 floats + pad; all fragment LDS conflict-free
#define PS_STR 68
#define ATTN_SMEM_BYTES ((4*64*KV_STR + 128*PS_STR) * 4)

__device__ __forceinline__ void load_kv_tile(float* Kbuf, float* Vbuf,
                                             const float* Kh, const float* Vh,
                                             int k0, int tid)
{
#pragma unroll
    for (int i = 0; i < 8; i++) {
        int idx = tid + i * 256;
        int row = idx >> 5, c16 = idx & 31;
        cpa16(Kbuf + row * KV_STR + c16 * 4, Kh + (size_t)(k0 + row) * HD_ + c16 * 4);
    }
#pragma unroll
    for (int i = 0; i < 8; i++) {
        int idx = tid + i * 256;
        int row = idx >> 5, c16 = idx & 31;
        cpa16(Vbuf + row * KV_STR + c16 * 4, Vh + (size_t)(k0 + row) * HD_ + c16 * 4);
    }
    cpa_commit();
}

__global__ __launch_bounds__(256, 1) void attn_kernel()
{
    extern __shared__ float sm[];
    float* Ks = sm;                         // [2][64][KV_STR]
    float* Vs = sm + 2 * 64 * KV_STR;       // [2][64][KV_STR]
    float* Ps = sm + 4 * 64 * KV_STR;       // [128][PS_STR]

    const int b = blockIdx.z, h = blockIdx.y;
    const int q0 = blockIdx.x * 128;
    const float* Qh = g_q + (((size_t)(b * H_ + h)) * T_) * HD_;
    const float* Kh = g_k + (((size_t)(b * H_ + h)) * T_) * HD_;
    const float* Vh = g_v + (((size_t)(b * H_ + h)) * T_) * HD_;

    const int tid = threadIdx.x;
    const int lane = tid & 31;
    const int w = tid >> 5;
    const int r1 = lane >> 2;       // 0..7
    const int cc = lane & 3;        // 0..3
    const int qrow1 = q0 + w * 16 + r1;
    const int qrow2 = qrow1 + 8;
    const int ntile = (q0 >> 6) + 2;

    // prefetch KV tile 0
    load_kv_tile(Ks, Vs, Kh, Vh, 0, tid);

    // Q fragments in registers (already tf32-rounded by rope)
    unsigned qf[16][4];
#pragma unroll
    for (int s = 0; s < 16; s++) {
        qf[s][0] = __float_as_uint(Qh[(size_t)qrow1 * HD_ + 8 * s + cc]);
        qf[s][1] = __float_as_uint(Qh[(size_t)qrow2 * HD_ + 8 * s + cc]);
        qf[s][2] = __float_as_uint(Qh[(size_t)qrow1 * HD_ + 8 * s + 4 + cc]);
        qf[s][3] = __float_as_uint(Qh[(size_t)qrow2 * HD_ + 8 * s + 4 + cc]);
    }

    float oacc[16][4];
#pragma unroll
    for (int n = 0; n < 16; n++)
#pragma unroll
        for (int e = 0; e < 4; e++) oacc[n][e] = 0.f;
    float m1 = -1e30f, m2 = -1e30f, l1 = 0.f, l2 = 0.f;
    const float sm_scale = 0.08838834764831845f;  // 1/sqrt(128)

    for (int t = 0; t < ntile; t++) {
        const int k0 = t * 64;
        float* Kb = Ks + (t & 1) * 64 * KV_STR;
        float* Vb = Vs + (t & 1) * 64 * KV_STR;

        if (t + 1 < ntile) {
            load_kv_tile(Ks + ((t + 1) & 1) * 64 * KV_STR,
                         Vs + ((t + 1) & 1) * 64 * KV_STR,
                         Kh, Vh, k0 + 64, tid);
            cpa_wait<1>();
        } else {
            cpa_wait<0>();
        }
        __syncthreads();

        // ---- S = Q K^T ----
        float sacc[8][4];
#pragma unroll
        for (int n = 0; n < 8; n++)
#pragma unroll
            for (int e = 0; e < 4; e++) sacc[n][e] = 0.f;

#pragma unroll
        for (int s = 0; s < 16; s++) {
#pragma unroll
            for (int n = 0; n < 8; n++) {
                unsigned b0 = __float_as_uint(Kb[(8 * n + r1) * KV_STR + 8 * s + cc]);
                unsigned b1 = __float_as_uint(Kb[(8 * n + r1) * KV_STR + 8 * s + 4 + cc]);
                mma_tf32(sacc[n], qf[s][0], qf[s][1], qf[s][2], qf[s][3], b0, b1);
            }
        }

        // ---- mask + online softmax ----
        const bool need_mask = (t >= ntile - 2);
        float mx1 = -1e30f, mx2 = -1e30f;
#pragma unroll
        for (int n = 0; n < 8; n++) {
            int col = k0 + 8 * n + 2 * cc;
            float s0 = sacc[n][0] * sm_scale;
            float s1 = sacc[n][1] * sm_scale;
            float s2 = sacc[n][2] * sm_scale;
            float s3 = sacc[n][3] * sm_scale;
            if (need_mask) {
                if (col     > qrow1) s0 = -1e30f;
                if (col + 1 > qrow1) s1 = -1e30f;
                if (col     > qrow2) s2 = -1e30f;
                if (col + 1 > qrow2) s3 = -1e30f;
            }
            sacc[n][0] = s0; sacc[n][1] = s1; sacc[n][2] = s2; sacc[n][3] = s3;
            mx1 = fmaxf(mx1, fmaxf(s0, s1));
            mx2 = fmaxf(mx2, fmaxf(s2, s3));
        }
        mx1 = fmaxf(mx1, __shfl_xor_sync(0xffffffffu, mx1, 1));
        mx1 = fmaxf(mx1, __shfl_xor_sync(0xffffffffu, mx1, 2));
        mx2 = fmaxf(mx2, __shfl_xor_sync(0xffffffffu, mx2, 1));
        mx2 = fmaxf(mx2, __shfl_xor_sync(0xffffffffu, mx2, 2));
        float mn1 = fmaxf(m1, mx1), mn2 = fmaxf(m2, mx2);

        float sum1 = 0.f, sum2 = 0.f;
#pragma unroll
        for (int n = 0; n < 8; n++) {
            float p0 = __uint_as_float(f2tf32(__expf(sacc[n][0] - mn1)));
            float p1 = __uint_as_float(f2tf32(__expf(sacc[n][1] - mn1)));
            float p2 = __uint_as_float(f2tf32(__expf(sacc[n][2] - mn2)));
            float p3 = __uint_as_float(f2tf32(__expf(sacc[n][3] - mn2)));
            sum1 += p0 + p1;
            sum2 += p2 + p3;
            *(float2*)&Ps[(w * 16 + r1) * PS_STR + 8 * n + 2 * cc]     = make_float2(p0, p1);
            *(float2*)&Ps[(w * 16 + r1 + 8) * PS_STR + 8 * n + 2 * cc] = make_float2(p2, p3);
        }
        sum1 += __shfl_xor_sync(0xffffffffu, sum1, 1);
        sum1 += __shfl_xor_sync(0xffffffffu, sum1, 2);
        sum2 += __shfl_xor_sync(0xffffffffu, sum2, 1);
        sum2 += __shfl_xor_sync(0xffffffffu, sum2, 2);

        float sc1 = __expf(m1 - mn1), sc2 = __expf(m2 - mn2);
        l1 = l1 * sc1 + sum1;
        l2 = l2 * sc2 + sum2;
        m1 = mn1; m2 = mn2;
#pragma unroll
        for (int n = 0; n < 16; n++) {
            oacc[n][0] *= sc1; oacc[n][1] *= sc1;
            oacc[n][2] *= sc2; oacc[n][3] *= sc2;
        }
        __syncwarp();

        // ---- O += P V ----
#pragma unroll
        for (int s = 0; s < 8; s++) {
            unsigned a0 = __float_as_uint(Ps[(w * 16 + r1) * PS_STR + 8 * s + cc]);
            unsigned a1 = __float_as_uint(Ps[(w * 16 + r1 + 8) * PS_STR + 8 * s + cc]);
            unsigned a2 = __float_as_uint(Ps[(w * 16 + r1) * PS_STR + 8 * s + 4 + cc]);
            unsigned a3 = __float_as_uint(Ps[(w * 16 + r1 + 8) * PS_STR + 8 * s + 4 + cc]);
#pragma unroll
            for (int n = 0; n < 16; n++) {
                unsigned b0 = __float_as_uint(Vb[(8 * s + cc) * KV_STR + 8 * n + r1]);
                unsigned b1 = __float_as_uint(Vb[(8 * s + 4 + cc) * KV_STR + 8 * n + r1]);
                mma_tf32(oacc[n], a0, a1, a2, a3, b0, b1);
            }
        }
        __syncthreads();
    }

    // ---- write y ----
    float inv1 = 1.0f / l1, inv2 = 1.0f / l2;
    float* y1 = g_y + ((size_t)b * T_ + qrow1) * D_ + h * HD_;
    float* y2 = g_y + ((size_t)b * T_ + qrow2) * D_ + h * HD_;
#pragma unroll
    for (int n = 0; n < 16; n++) {
        int col = 8 * n + 2 * cc;
        *(float2*)(y1 + col) = make_float2(oacc[n][0] * inv1, oacc[n][1] * inv1);
        *(float2*)(y2 + col) = make_float2(oacc[n][2] * inv2, oacc[n][3] * inv2);
    }
}

// ============================================================================
extern "C" void kernel_launch(void* const* d_in, const int* in_sizes, int n_in,
                              void* d_out, int out_size)
{
    const float* x     = (const float*)d_in[0];
    const float* w_qkv = (const float*)d_in[1];
    const float* w_out = (const float*)d_in[2];
    float* out = (float*)d_out;

    cudaFuncSetAttribute(attn_kernel, cudaFuncAttributeMaxDynamicSharedMemorySize,
                         ATTN_SMEM_BYTES);

    dim3 g1(6144 / 128, (B_ * T_) / 128);
    gemm_qkv_kernel<<<g1, 256>>>(x, w_qkv);

    int total_pairs = B_ * H_ * T_ * (HD_ / 2);
    rope_kernel<<<(total_pairs + 255) / 256, 256>>>();

    dim3 g2(T_ / 128, H_, B_);
    attn_kernel<<<g2, 256, ATTN_SMEM_BYTES>>>();

    dim3 g3(D_ / 128, (B_ * T_) / 128);
    gemm_out_kernel<<<g3, 256>>>(w_out, out);
}